// round 13
// baseline (speedup 1.0000x reference)
#include <cuda_runtime.h>
#include <cuda_bf16.h>
#include <mma.h>
#include <cstdint>

using namespace nvcuda;

#define NN 100000
#define NE 1600000
constexpr int NN_PAD = 100096;          // 782 * 128
constexpr int IN_C  = 64;
constexpr int HID_C = 128;
constexpr int OUT_C = 64;

// ---------------- scratch (device globals; no allocation allowed) ----------------
__device__                int   g_is64;          // 1 if edge_index is int64-laid-out
__device__                int   g_total;         // slab allocator cursor
__device__ __align__(16) int   g_cnt [NN];      // in-degree (excl self)
__device__ __align__(16) int   g_rowS[NN];      // CSR slab start
__device__ __align__(16) int   g_cur [NN];      // fill cursor
__device__ __align__(16) float g_dinv[NN];
__device__ __align__(16) int2  g_csr [NE];      // {src, norm bits}
__device__ __align__(16) float g_agg1[(size_t)NN_PAD * IN_C];   // A_hat @ x  (padded)
__device__ __align__(16) float g_h   [(size_t)NN_PAD * HID_C];  // relu(...)  (padded)
__device__ __align__(16) float g_hw  [(size_t)NN_PAD * OUT_C];  // h @ W4     (padded)

__device__ __forceinline__ int clampi(int v, int lo, int hi) {
    return min(max(v, lo), hi);
}

// ---------------- prep: fused detect + zero ----------------
__global__ void k_detect_zero(const int* __restrict__ ei32, int n) {
    int i = blockIdx.x * blockDim.x + threadIdx.x;
    if (i < n) g_cnt[i] = 0;
    if (i == 0) g_total = 0;
    if (blockIdx.x == 0) {
        __shared__ int bad;
        if (threadIdx.x == 0) bad = 0;
        __syncthreads();
        if (ei32[2 * threadIdx.x + 1] != 0) bad = 1;
        __syncthreads();
        if (threadIdx.x == 0) g_is64 = bad ? 0 : 1;
    }
}

__device__ __forceinline__ int load_src(const int* __restrict__ ei32, int e, int ne, int is64) {
    return is64 ? ei32[(size_t)2 * e] : ei32[e];
}
__device__ __forceinline__ int load_dst(const int* __restrict__ ei32, int e, int ne, int is64) {
    return is64 ? ei32[(size_t)2 * (ne + e)] : ei32[(size_t)ne + e];
}

__global__ void k_hist(const int* __restrict__ ei32, int ne, int n) {
    int e = blockIdx.x * blockDim.x + threadIdx.x;
    if (e < ne) {
        int is64 = g_is64;
        int d = clampi(load_dst(ei32, e, ne, is64), 0, n - 1);
        atomicAdd(&g_cnt[d], 1);
    }
}

__global__ void k_dinv_alloc(int n) {
    int i = blockIdx.x * blockDim.x + threadIdx.x;
    if (i < n) {
        int c = g_cnt[i];
        g_dinv[i] = rsqrtf((float)(c + 1));       // +1 self-loop
        int r = atomicAdd(&g_total, c);           // slab (order-free)
        g_rowS[i] = r;
        g_cur[i]  = r;
    }
}

__global__ void k_fill(const int* __restrict__ ei32, int ne, int n) {
    int e = blockIdx.x * blockDim.x + threadIdx.x;
    if (e < ne) {
        int is64 = g_is64;
        int s = clampi(load_src(ei32, e, ne, is64), 0, n - 1);
        int d = clampi(load_dst(ei32, e, ne, is64), 0, n - 1);
        int pos = atomicAdd(&g_cur[d], 1);
        if (pos >= 0 && pos < ne) {
            float w = g_dinv[s] * g_dinv[d];
            g_csr[pos] = make_int2(s, __float_as_int(w));
        }
    }
}

// ---------------- aggregation: warp per node ----------------
template <bool BIAS>
__device__ __forceinline__ void agg_body(const float* __restrict__ feat,
                                         float* __restrict__ outp,
                                         const float* __restrict__ bias, int n, int ne) {
    int t    = blockIdx.x * blockDim.x + threadIdx.x;
    int node = t >> 5;
    int lane = t & 31;
    int c4   = lane & 15;
    int half = lane >> 4;
    if (node >= n) return;
    const float4* f4 = (const float4*)feat;

    float4 acc = make_float4(0.f, 0.f, 0.f, 0.f);
    if (half == 0) {
        float di = g_dinv[node];
        float sc = di * di;
        float4 v = __ldg(f4 + (size_t)node * 16 + c4);
        acc.x = v.x * sc; acc.y = v.y * sc; acc.z = v.z * sc; acc.w = v.w * sc;
        if (BIAS) {
            float4 bv = *(const float4*)(bias + c4 * 4);
            acc.x += bv.x; acc.y += bv.y; acc.z += bv.z; acc.w += bv.w;
        }
    }

    int beg = clampi(g_rowS[node], 0, ne);
    int end = clampi(beg + g_cnt[node], 0, ne);
    for (int k = beg + half; k < end; k += 2) {
        int2  en = __ldg(&g_csr[k]);
        int   s  = clampi(en.x, 0, n - 1);
        float w  = __int_as_float(en.y);
        float4 v = __ldg(f4 + (size_t)s * 16 + c4);
        acc.x += w * v.x; acc.y += w * v.y;
        acc.z += w * v.z; acc.w += w * v.w;
    }

    acc.x += __shfl_down_sync(0xffffffffu, acc.x, 16);
    acc.y += __shfl_down_sync(0xffffffffu, acc.y, 16);
    acc.z += __shfl_down_sync(0xffffffffu, acc.z, 16);
    acc.w += __shfl_down_sync(0xffffffffu, acc.w, 16);

    if (half == 0)
        *(float4*)(outp + (size_t)node * 64 + c4 * 4) = acc;
}

__global__ void k_agg_l1(const float* __restrict__ x, int n, int ne) {
    agg_body<false>(x, g_agg1, nullptr, n, ne);
}
__global__ void k_agg_l2(float* __restrict__ out, const float* __restrict__ b4, int n, int ne) {
    agg_body<true>(g_hw, out, b4, n, ne);
}

// ---------------- bf16 split helper ----------------
__device__ __forceinline__ void bf16_split(float v, __nv_bfloat16& h, __nv_bfloat16& l) {
    h = __float2bfloat16(v);
    l = __float2bfloat16(v - __bfloat162float(h));
}

// ---------------- GEMM1 (wmma): g_h = relu(g_agg1[tile,64] @ W3[64,128] + b3) ------
// 3-pass hi/lo bf16: hh + hl + lh accumulated in fp32.
constexpr int G1_SMEM = (128 * 64 * 2 + 64 * 128 * 2) * 2 + 16 * 128 * 4;  // 73728

__global__ void __launch_bounds__(256) k_gemm1_wmma(const float* __restrict__ W3,
                                                    const float* __restrict__ b3) {
    extern __shared__ __align__(16) char smem[];
    __nv_bfloat16* AH = (__nv_bfloat16*)smem;           // [128][64]
    __nv_bfloat16* AL = AH + 128 * 64;
    __nv_bfloat16* BH = AL + 128 * 64;                   // [64][128]
    __nv_bfloat16* BL = BH + 64 * 128;
    float* biasT      = (float*)(BL + 64 * 128);         // [16][128]

    int tid = threadIdx.x;
    int rb  = blockIdx.x * 128;

    for (int i = tid; i < 128 * 64; i += 256) {
        int r = i >> 6, c = i & 63;
        bf16_split(g_agg1[(size_t)(rb + r) * 64 + c], AH[i], AL[i]);
    }
    for (int i = tid; i < 64 * 128; i += 256) {
        bf16_split(__ldg(&W3[i]), BH[i], BL[i]);         // W3 row-major [64][128]
    }
    for (int i = tid; i < 16 * 128; i += 256) biasT[i] = b3[i & 127];
    __syncthreads();

    int w = tid >> 5;                                    // warp = 16-row strip
    wmma::fragment<wmma::accumulator, 16, 16, 16, float> acc[8];
#pragma unroll
    for (int c = 0; c < 8; c++)
        wmma::load_matrix_sync(acc[c], biasT + c * 16, 128, wmma::mem_row_major);

#pragma unroll
    for (int pass = 0; pass < 3; pass++) {
        const __nv_bfloat16* Ap = (pass == 2) ? AL : AH;
        const __nv_bfloat16* Bp = (pass == 1) ? BL : BH;
#pragma unroll
        for (int k = 0; k < 4; k++) {
            wmma::fragment<wmma::matrix_a, 16, 16, 16, __nv_bfloat16, wmma::row_major> a;
            wmma::load_matrix_sync(a, Ap + (w * 16) * 64 + k * 16, 64);
#pragma unroll
            for (int c = 0; c < 8; c++) {
                wmma::fragment<wmma::matrix_b, 16, 16, 16, __nv_bfloat16, wmma::row_major> b;
                wmma::load_matrix_sync(b, Bp + (k * 16) * 128 + c * 16, 128);
                wmma::mma_sync(acc[c], a, b, acc[c]);
            }
        }
    }

#pragma unroll
    for (int c = 0; c < 8; c++) {
#pragma unroll
        for (int e = 0; e < acc[c].num_elements; e++)
            acc[c].x[e] = fmaxf(acc[c].x[e], 0.f);
        wmma::store_matrix_sync(g_h + (size_t)(rb + w * 16) * HID_C + c * 16,
                                acc[c], HID_C, wmma::mem_row_major);
    }
}

// ---------------- GEMM2 (wmma): g_hw = g_h[tile,128] @ W4[128,64] ------------------
constexpr int G2_SMEM = (128 * 128 * 2 + 128 * 64 * 2) * 2;  // 98304

__global__ void __launch_bounds__(256) k_gemm2_wmma(const float* __restrict__ W4) {
    extern __shared__ __align__(16) char smem[];
    __nv_bfloat16* AH = (__nv_bfloat16*)smem;           // [128][128]
    __nv_bfloat16* AL = AH + 128 * 128;
    __nv_bfloat16* BH = AL + 128 * 128;                  // [128][64]
    __nv_bfloat16* BL = BH + 128 * 64;

    int tid = threadIdx.x;
    int rb  = blockIdx.x * 128;

    for (int i = tid; i < 128 * 128; i += 256) {
        int r = i >> 7, c = i & 127;
        bf16_split(g_h[(size_t)(rb + r) * HID_C + c], AH[i], AL[i]);
    }
    for (int i = tid; i < 128 * 64; i += 256) {
        bf16_split(__ldg(&W4[i]), BH[i], BL[i]);         // W4 row-major [128][64]
    }
    __syncthreads();

    int w = tid >> 5;
    wmma::fragment<wmma::accumulator, 16, 16, 16, float> acc[4];
#pragma unroll
    for (int c = 0; c < 4; c++) wmma::fill_fragment(acc[c], 0.0f);

#pragma unroll
    for (int pass = 0; pass < 3; pass++) {
        const __nv_bfloat16* Ap = (pass == 2) ? AL : AH;
        const __nv_bfloat16* Bp = (pass == 1) ? BL : BH;
#pragma unroll
        for (int k = 0; k < 8; k++) {
            wmma::fragment<wmma::matrix_a, 16, 16, 16, __nv_bfloat16, wmma::row_major> a;
            wmma::load_matrix_sync(a, Ap + (w * 16) * 128 + k * 16, 128);
#pragma unroll
            for (int c = 0; c < 4; c++) {
                wmma::fragment<wmma::matrix_b, 16, 16, 16, __nv_bfloat16, wmma::row_major> b;
                wmma::load_matrix_sync(b, Bp + (k * 16) * 64 + c * 16, 64);
                wmma::mma_sync(acc[c], a, b, acc[c]);
            }
        }
    }

#pragma unroll
    for (int c = 0; c < 4; c++)
        wmma::store_matrix_sync(g_hw + (size_t)(rb + w * 16) * OUT_C + c * 16,
                                acc[c], OUT_C, wmma::mem_row_major);
}

// ---------------- launch ----------------
extern "C" void kernel_launch(void* const* d_in, const int* in_sizes, int n_in,
                              void* d_out, int out_size) {
    const float* x    = (const float*)d_in[0];
    const int*   ei32 = (const int*)d_in[1];     // int32 OR int64 layout; probed on device
    const float* W3   = (const float*)d_in[2];
    const float* b3   = (const float*)d_in[3];
    const float* W4   = (const float*)d_in[4];
    const float* b4   = (const float*)d_in[5];
    float* out = (float*)d_out;

    int nn = in_sizes[0] / IN_C;   // 100000
    int ne = in_sizes[1] / 2;      // 1600000

    const int B  = 256;
    const int gN = (nn + B - 1) / B;
    const int gE = (ne + B - 1) / B;
    const int gA = (int)(((long long)nn * 32 + B - 1) / B);   // warp per node
    const int gT = NN_PAD / 128;                              // 782 tiles

    cudaFuncSetAttribute(k_gemm1_wmma, cudaFuncAttributeMaxDynamicSharedMemorySize, G1_SMEM);
    cudaFuncSetAttribute(k_gemm2_wmma, cudaFuncAttributeMaxDynamicSharedMemorySize, G2_SMEM);

    // CSR build
    k_detect_zero<<<gN, B>>>(ei32, nn);
    k_hist<<<gE, B>>>(ei32, ne, nn);
    k_dinv_alloc<<<gN, B>>>(nn);
    k_fill<<<gE, B>>>(ei32, ne, nn);

    // layer 1: agg1 = A_hat @ x ; h = relu(agg1 @ W3 + b3)
    k_agg_l1<<<gA, B>>>(x, nn, ne);
    k_gemm1_wmma<<<gT, 256, G1_SMEM>>>(W3, b3);

    // layer 2: hw = h @ W4 ; out = A_hat @ hw + b4
    k_gemm2_wmma<<<gT, 256, G2_SMEM>>>(W4);
    k_agg_l2<<<gA, B>>>(out, b4, nn, ne);
}

// round 14
// speedup vs baseline: 1.9452x; 1.9452x over previous
#include <cuda_runtime.h>
#include <cuda_bf16.h>
#include <mma.h>
#include <cstdint>

using namespace nvcuda;

#define NN 100000
#define NE 1600000
constexpr int NN_PAD = 100096;          // 782 * 128
constexpr int IN_C  = 64;
constexpr int HID_C = 128;
constexpr int OUT_C = 64;

// ---------------- scratch (device globals; no allocation allowed) ----------------
__device__                int   g_is64;          // 1 if edge_index is int64-laid-out
__device__                int   g_total;         // slab allocator cursor
__device__ __align__(16) int   g_cnt [NN];      // in-degree (excl self)
__device__ __align__(16) int   g_rowS[NN];      // CSR slab start
__device__ __align__(16) int   g_cur [NN];      // fill cursor
__device__ __align__(16) float g_dinv[NN];
__device__ __align__(16) int2  g_csr [NE];      // {src, norm bits}
__device__ __align__(16) float g_agg1[(size_t)NN_PAD * IN_C];   // A_hat @ x  (padded)
__device__ __align__(16) float g_h   [(size_t)NN_PAD * HID_C];  // relu(...)  (padded)
__device__ __align__(16) float g_hw  [(size_t)NN_PAD * OUT_C];  // h @ W4     (padded)

__device__ __forceinline__ int clampi(int v, int lo, int hi) {
    return min(max(v, lo), hi);
}

// ---------------- prep: fused detect + zero ----------------
__global__ void k_detect_zero(const int* __restrict__ ei32, int n) {
    int i = blockIdx.x * blockDim.x + threadIdx.x;
    if (i < n) g_cnt[i] = 0;
    if (i == 0) g_total = 0;
    if (blockIdx.x == 0) {
        __shared__ int bad;
        if (threadIdx.x == 0) bad = 0;
        __syncthreads();
        if (ei32[2 * threadIdx.x + 1] != 0) bad = 1;
        __syncthreads();
        if (threadIdx.x == 0) g_is64 = bad ? 0 : 1;
    }
}

// ---------------- histogram: 4 edges per thread, int4 loads on int32 path --------
__global__ void k_hist(const int* __restrict__ ei32, int ne, int n) {
    int e0 = (blockIdx.x * blockDim.x + threadIdx.x) * 4;
    if (e0 >= ne) return;
    if (g_is64) {
        for (int j = 0; j < 4; j++) {
            int e = e0 + j;
            if (e < ne) {
                int d = clampi(ei32[(size_t)2 * (ne + e)], 0, n - 1);
                atomicAdd(&g_cnt[d], 1);
            }
        }
    } else if (e0 + 3 < ne) {
        int4 dv = *(const int4*)(ei32 + (size_t)ne + e0);
        atomicAdd(&g_cnt[clampi(dv.x, 0, n - 1)], 1);
        atomicAdd(&g_cnt[clampi(dv.y, 0, n - 1)], 1);
        atomicAdd(&g_cnt[clampi(dv.z, 0, n - 1)], 1);
        atomicAdd(&g_cnt[clampi(dv.w, 0, n - 1)], 1);
    } else {
        for (int e = e0; e < ne; e++) {
            int d = clampi(ei32[(size_t)ne + e], 0, n - 1);
            atomicAdd(&g_cnt[d], 1);
        }
    }
}

__global__ void k_dinv_alloc(int n) {
    int i = blockIdx.x * blockDim.x + threadIdx.x;
    if (i < n) {
        int c = g_cnt[i];
        g_dinv[i] = rsqrtf((float)(c + 1));       // +1 self-loop
        int r = atomicAdd(&g_total, c);           // slab (order-free)
        g_rowS[i] = r;
        g_cur[i]  = r;
    }
}

// ---------------- CSR fill: 4 edges per thread ----------------
__device__ __forceinline__ void fill_one(int s, int d, int ne, int n) {
    s = clampi(s, 0, n - 1);
    d = clampi(d, 0, n - 1);
    int pos = atomicAdd(&g_cur[d], 1);
    if (pos >= 0 && pos < ne) {
        float w = g_dinv[s] * g_dinv[d];
        g_csr[pos] = make_int2(s, __float_as_int(w));
    }
}

__global__ void k_fill(const int* __restrict__ ei32, int ne, int n) {
    int e0 = (blockIdx.x * blockDim.x + threadIdx.x) * 4;
    if (e0 >= ne) return;
    if (g_is64) {
        for (int j = 0; j < 4; j++) {
            int e = e0 + j;
            if (e < ne)
                fill_one(ei32[(size_t)2 * e], ei32[(size_t)2 * (ne + e)], ne, n);
        }
    } else if (e0 + 3 < ne) {
        int4 sv = *(const int4*)(ei32 + e0);
        int4 dv = *(const int4*)(ei32 + (size_t)ne + e0);
        fill_one(sv.x, dv.x, ne, n);
        fill_one(sv.y, dv.y, ne, n);
        fill_one(sv.z, dv.z, ne, n);
        fill_one(sv.w, dv.w, ne, n);
    } else {
        for (int e = e0; e < ne; e++)
            fill_one(ei32[e], ei32[(size_t)ne + e], ne, n);
    }
}

// ---------------- aggregation: warp per node (R11 design) ----------------
template <bool BIAS>
__device__ __forceinline__ void agg_body(const float* __restrict__ feat,
                                         float* __restrict__ outp,
                                         const float* __restrict__ bias, int n, int ne) {
    int t    = blockIdx.x * blockDim.x + threadIdx.x;
    int node = t >> 5;
    int lane = t & 31;
    int c4   = lane & 15;
    int half = lane >> 4;
    if (node >= n) return;
    const float4* f4 = (const float4*)feat;

    float4 acc = make_float4(0.f, 0.f, 0.f, 0.f);
    if (half == 0) {
        float di = g_dinv[node];
        float sc = di * di;
        float4 v = __ldg(f4 + (size_t)node * 16 + c4);
        acc.x = v.x * sc; acc.y = v.y * sc; acc.z = v.z * sc; acc.w = v.w * sc;
        if (BIAS) {
            float4 bv = *(const float4*)(bias + c4 * 4);
            acc.x += bv.x; acc.y += bv.y; acc.z += bv.z; acc.w += bv.w;
        }
    }

    int beg = clampi(g_rowS[node], 0, ne);
    int end = clampi(beg + g_cnt[node], 0, ne);
    for (int k = beg + half; k < end; k += 2) {
        int2  en = __ldg(&g_csr[k]);
        int   s  = clampi(en.x, 0, n - 1);
        float w  = __int_as_float(en.y);
        float4 v = __ldg(f4 + (size_t)s * 16 + c4);
        acc.x += w * v.x; acc.y += w * v.y;
        acc.z += w * v.z; acc.w += w * v.w;
    }

    acc.x += __shfl_down_sync(0xffffffffu, acc.x, 16);
    acc.y += __shfl_down_sync(0xffffffffu, acc.y, 16);
    acc.z += __shfl_down_sync(0xffffffffu, acc.z, 16);
    acc.w += __shfl_down_sync(0xffffffffu, acc.w, 16);

    if (half == 0)
        *(float4*)(outp + (size_t)node * 64 + c4 * 4) = acc;
}

__global__ void k_agg_l1(const float* __restrict__ x, int n, int ne) {
    agg_body<false>(x, g_agg1, nullptr, n, ne);
}
__global__ void k_agg_l2(float* __restrict__ out, const float* __restrict__ b4, int n, int ne) {
    agg_body<true>(g_hw, out, b4, n, ne);
}

// ---------------- bf16 split helper ----------------
__device__ __forceinline__ void bf16_split(float v, __nv_bfloat16& h, __nv_bfloat16& l) {
    h = __float2bfloat16(v);
    l = __float2bfloat16(v - __bfloat162float(h));
}

// ---------------- GEMM1 (wmma): g_h = relu(g_agg1[tile,64] @ W3[64,128] + b3) ------
// 3-pass hi/lo bf16 (hh + hl + lh), fp32 accum. PADDED smem strides: conflict-free.
constexpr int A1_LD = 72;    // 64 + 8  (bf16 elems)
constexpr int B1_LD = 136;   // 128 + 8
constexpr int G1_SMEM = (2 * 128 * A1_LD + 2 * 64 * B1_LD) * 2 + 16 * B1_LD * 4;

__global__ void __launch_bounds__(256) k_gemm1_wmma(const float* __restrict__ W3,
                                                    const float* __restrict__ b3) {
    extern __shared__ __align__(16) char smem[];
    __nv_bfloat16* AH = (__nv_bfloat16*)smem;            // [128][A1_LD]
    __nv_bfloat16* AL = AH + 128 * A1_LD;
    __nv_bfloat16* BH = AL + 128 * A1_LD;                // [64][B1_LD]
    __nv_bfloat16* BL = BH + 64 * B1_LD;
    float* biasT      = (float*)(BL + 64 * B1_LD);       // [16][B1_LD]

    int tid = threadIdx.x;
    int rb  = blockIdx.x * 128;

    for (int i = tid; i < 128 * 64; i += 256) {
        int r = i >> 6, c = i & 63;
        bf16_split(g_agg1[(size_t)(rb + r) * 64 + c], AH[r * A1_LD + c], AL[r * A1_LD + c]);
    }
    for (int i = tid; i < 64 * 128; i += 256) {
        int k = i >> 7, nn2 = i & 127;
        bf16_split(__ldg(&W3[i]), BH[k * B1_LD + nn2], BL[k * B1_LD + nn2]);
    }
    for (int i = tid; i < 16 * 128; i += 256) biasT[(i >> 7) * B1_LD + (i & 127)] = b3[i & 127];
    __syncthreads();

    int w = tid >> 5;                                    // warp = 16-row strip
    wmma::fragment<wmma::accumulator, 16, 16, 16, float> acc[8];
#pragma unroll
    for (int c = 0; c < 8; c++)
        wmma::load_matrix_sync(acc[c], biasT + c * 16, B1_LD, wmma::mem_row_major);

#pragma unroll
    for (int pass = 0; pass < 3; pass++) {
        const __nv_bfloat16* Ap = (pass == 2) ? AL : AH;
        const __nv_bfloat16* Bp = (pass == 1) ? BL : BH;
#pragma unroll
        for (int k = 0; k < 4; k++) {
            wmma::fragment<wmma::matrix_a, 16, 16, 16, __nv_bfloat16, wmma::row_major> a;
            wmma::load_matrix_sync(a, Ap + (w * 16) * A1_LD + k * 16, A1_LD);
#pragma unroll
            for (int c = 0; c < 8; c++) {
                wmma::fragment<wmma::matrix_b, 16, 16, 16, __nv_bfloat16, wmma::row_major> b;
                wmma::load_matrix_sync(b, Bp + (k * 16) * B1_LD + c * 16, B1_LD);
                wmma::mma_sync(acc[c], a, b, acc[c]);
            }
        }
    }

#pragma unroll
    for (int c = 0; c < 8; c++) {
#pragma unroll
        for (int e = 0; e < acc[c].num_elements; e++)
            acc[c].x[e] = fmaxf(acc[c].x[e], 0.f);
        wmma::store_matrix_sync(g_h + (size_t)(rb + w * 16) * HID_C + c * 16,
                                acc[c], HID_C, wmma::mem_row_major);
    }
}

// ---------------- GEMM2 (wmma): g_hw = g_h[tile,128] @ W4[128,64] ------------------
constexpr int A2_LD = 136;   // 128 + 8
constexpr int B2_LD = 72;    // 64 + 8
constexpr int G2_SMEM = (2 * 128 * A2_LD + 2 * 128 * B2_LD) * 2;

__global__ void __launch_bounds__(256) k_gemm2_wmma(const float* __restrict__ W4) {
    extern __shared__ __align__(16) char smem[];
    __nv_bfloat16* AH = (__nv_bfloat16*)smem;            // [128][A2_LD]
    __nv_bfloat16* AL = AH + 128 * A2_LD;
    __nv_bfloat16* BH = AL + 128 * A2_LD;                // [128][B2_LD]
    __nv_bfloat16* BL = BH + 128 * B2_LD;

    int tid = threadIdx.x;
    int rb  = blockIdx.x * 128;

    for (int i = tid; i < 128 * 128; i += 256) {
        int r = i >> 7, c = i & 127;
        bf16_split(g_h[(size_t)(rb + r) * HID_C + c], AH[r * A2_LD + c], AL[r * A2_LD + c]);
    }
    for (int i = tid; i < 128 * 64; i += 256) {
        int k = i >> 6, nn2 = i & 63;
        bf16_split(__ldg(&W4[i]), BH[k * B2_LD + nn2], BL[k * B2_LD + nn2]);
    }
    __syncthreads();

    int w = tid >> 5;
    wmma::fragment<wmma::accumulator, 16, 16, 16, float> acc[4];
#pragma unroll
    for (int c = 0; c < 4; c++) wmma::fill_fragment(acc[c], 0.0f);

#pragma unroll
    for (int pass = 0; pass < 3; pass++) {
        const __nv_bfloat16* Ap = (pass == 2) ? AL : AH;
        const __nv_bfloat16* Bp = (pass == 1) ? BL : BH;
#pragma unroll
        for (int k = 0; k < 8; k++) {
            wmma::fragment<wmma::matrix_a, 16, 16, 16, __nv_bfloat16, wmma::row_major> a;
            wmma::load_matrix_sync(a, Ap + (w * 16) * A2_LD + k * 16, A2_LD);
#pragma unroll
            for (int c = 0; c < 4; c++) {
                wmma::fragment<wmma::matrix_b, 16, 16, 16, __nv_bfloat16, wmma::row_major> b;
                wmma::load_matrix_sync(b, Bp + (k * 16) * B2_LD + c * 16, B2_LD);
                wmma::mma_sync(acc[c], a, b, acc[c]);
            }
        }
    }

#pragma unroll
    for (int c = 0; c < 4; c++)
        wmma::store_matrix_sync(g_hw + (size_t)(rb + w * 16) * OUT_C + c * 16,
                                acc[c], OUT_C, wmma::mem_row_major);
}

// ---------------- launch ----------------
extern "C" void kernel_launch(void* const* d_in, const int* in_sizes, int n_in,
                              void* d_out, int out_size) {
    const float* x    = (const float*)d_in[0];
    const int*   ei32 = (const int*)d_in[1];     // int32 OR int64 layout; probed on device
    const float* W3   = (const float*)d_in[2];
    const float* b3   = (const float*)d_in[3];
    const float* W4   = (const float*)d_in[4];
    const float* b4   = (const float*)d_in[5];
    float* out = (float*)d_out;

    int nn = in_sizes[0] / IN_C;   // 100000
    int ne = in_sizes[1] / 2;      // 1600000

    const int B  = 256;
    const int gN = (nn + B - 1) / B;
    const int gE4 = (ne / 4 + B - 1) / B;                     // 4 edges per thread
    const int gA = (int)(((long long)nn * 32 + B - 1) / B);   // warp per node
    const int gT = NN_PAD / 128;                              // 782 tiles

    cudaFuncSetAttribute(k_gemm1_wmma, cudaFuncAttributeMaxDynamicSharedMemorySize, G1_SMEM);
    cudaFuncSetAttribute(k_gemm2_wmma, cudaFuncAttributeMaxDynamicSharedMemorySize, G2_SMEM);

    // CSR build
    k_detect_zero<<<gN, B>>>(ei32, nn);
    k_hist<<<gE4, B>>>(ei32, ne, nn);
    k_dinv_alloc<<<gN, B>>>(nn);
    k_fill<<<gE4, B>>>(ei32, ne, nn);

    // layer 1: agg1 = A_hat @ x ; h = relu(agg1 @ W3 + b3)
    k_agg_l1<<<gA, B>>>(x, nn, ne);
    k_gemm1_wmma<<<gT, 256, G1_SMEM>>>(W3, b3);

    // layer 2: hw = h @ W4 ; out = A_hat @ hw + b4
    k_gemm2_wmma<<<gT, 256, G2_SMEM>>>(W4);
    k_agg_l2<<<gA, B>>>(out, b4, nn, ne);
}

// round 15
// speedup vs baseline: 2.2679x; 1.1659x over previous
#include <cuda_runtime.h>
#include <cuda_bf16.h>
#include <mma.h>
#include <cstdint>

using namespace nvcuda;

#define NN 100000
#define NE 1600000
constexpr int NN_PAD = 100096;          // 782 * 128
constexpr int IN_C  = 64;
constexpr int HID_C = 128;
constexpr int OUT_C = 64;

// ---------------- scratch (device globals; no allocation allowed) ----------------
__device__                int   g_is64;          // 1 if edge_index is int64-laid-out
__device__                int   g_total;         // slab allocator cursor
__device__ __align__(16) int   g_cnt [NN];      // in-degree (excl self)
__device__ __align__(16) int   g_rowS[NN];      // CSR slab start
__device__ __align__(16) int   g_cur [NN];      // fill cursor
__device__ __align__(16) float g_dinv[NN];
__device__ __align__(16) int   g_csr_src[NE];   // src-only CSR entries
__device__ __align__(16) float g_agg1[(size_t)NN_PAD * IN_C];   // A_hat @ x  (padded)
__device__ __align__(16) float g_hw  [(size_t)NN_PAD * OUT_C];  // (relu(agg1 W3+b3)) W4

__device__ __forceinline__ int clampi(int v, int lo, int hi) {
    return min(max(v, lo), hi);
}

// ---------------- prep: fused detect + zero ----------------
__global__ void k_detect_zero(const int* __restrict__ ei32, int n) {
    int i = blockIdx.x * blockDim.x + threadIdx.x;
    if (i < n) g_cnt[i] = 0;
    if (i == 0) g_total = 0;
    if (blockIdx.x == 0) {
        __shared__ int bad;
        if (threadIdx.x == 0) bad = 0;
        __syncthreads();
        if (ei32[2 * threadIdx.x + 1] != 0) bad = 1;
        __syncthreads();
        if (threadIdx.x == 0) g_is64 = bad ? 0 : 1;
    }
}

// ---------------- histogram: 4 edges per thread, int4 loads on int32 path --------
__global__ void k_hist(const int* __restrict__ ei32, int ne, int n) {
    int e0 = (blockIdx.x * blockDim.x + threadIdx.x) * 4;
    if (e0 >= ne) return;
    if (g_is64) {
        for (int j = 0; j < 4; j++) {
            int e = e0 + j;
            if (e < ne) {
                int d = clampi(ei32[(size_t)2 * (ne + e)], 0, n - 1);
                atomicAdd(&g_cnt[d], 1);
            }
        }
    } else if (e0 + 3 < ne) {
        int4 dv = *(const int4*)(ei32 + (size_t)ne + e0);
        atomicAdd(&g_cnt[clampi(dv.x, 0, n - 1)], 1);
        atomicAdd(&g_cnt[clampi(dv.y, 0, n - 1)], 1);
        atomicAdd(&g_cnt[clampi(dv.z, 0, n - 1)], 1);
        atomicAdd(&g_cnt[clampi(dv.w, 0, n - 1)], 1);
    } else {
        for (int e = e0; e < ne; e++) {
            int d = clampi(ei32[(size_t)ne + e], 0, n - 1);
            atomicAdd(&g_cnt[d], 1);
        }
    }
}

__global__ void k_dinv_alloc(int n) {
    int i = blockIdx.x * blockDim.x + threadIdx.x;
    if (i < n) {
        int c = g_cnt[i];
        g_dinv[i] = rsqrtf((float)(c + 1));       // +1 self-loop
        int r = atomicAdd(&g_total, c);           // slab (order-free)
        g_rowS[i] = r;
        g_cur[i]  = r;
    }
}

// ---------------- CSR fill (src-only, no norm): 4 edges per thread --------------
__device__ __forceinline__ void fill_one(int s, int d, int ne, int n) {
    s = clampi(s, 0, n - 1);
    d = clampi(d, 0, n - 1);
    int pos = atomicAdd(&g_cur[d], 1);
    if (pos >= 0 && pos < ne) g_csr_src[pos] = s;
}

__global__ void k_fill(const int* __restrict__ ei32, int ne, int n) {
    int e0 = (blockIdx.x * blockDim.x + threadIdx.x) * 4;
    if (e0 >= ne) return;
    if (g_is64) {
        for (int j = 0; j < 4; j++) {
            int e = e0 + j;
            if (e < ne)
                fill_one(ei32[(size_t)2 * e], ei32[(size_t)2 * (ne + e)], ne, n);
        }
    } else if (e0 + 3 < ne) {
        int4 sv = *(const int4*)(ei32 + e0);
        int4 dv = *(const int4*)(ei32 + (size_t)ne + e0);
        fill_one(sv.x, dv.x, ne, n);
        fill_one(sv.y, dv.y, ne, n);
        fill_one(sv.z, dv.z, ne, n);
        fill_one(sv.w, dv.w, ne, n);
    } else {
        for (int e = e0; e < ne; e++)
            fill_one(ei32[e], ei32[(size_t)ne + e], ne, n);
    }
}

// ---------------- aggregation: warp per node ----------------
// out[n] = dinv[n]^2*feat[n] (+bias) + sum_e dinv[src]*dinv[n]*feat[src]
template <bool BIAS>
__device__ __forceinline__ void agg_body(const float* __restrict__ feat,
                                         float* __restrict__ outp,
                                         const float* __restrict__ bias, int n, int ne) {
    int t    = blockIdx.x * blockDim.x + threadIdx.x;
    int node = t >> 5;
    int lane = t & 31;
    int c4   = lane & 15;
    int half = lane >> 4;
    if (node >= n) return;
    const float4* f4 = (const float4*)feat;

    float dnode = g_dinv[node];
    float4 acc = make_float4(0.f, 0.f, 0.f, 0.f);
    if (half == 0) {
        float sc = dnode * dnode;
        float4 v = __ldg(f4 + (size_t)node * 16 + c4);
        acc.x = v.x * sc; acc.y = v.y * sc; acc.z = v.z * sc; acc.w = v.w * sc;
        if (BIAS) {
            float4 bv = *(const float4*)(bias + c4 * 4);
            acc.x += bv.x; acc.y += bv.y; acc.z += bv.z; acc.w += bv.w;
        }
    }

    int beg = clampi(g_rowS[node], 0, ne);
    int end = clampi(beg + g_cnt[node], 0, ne);
    for (int k = beg + half; k < end; k += 2) {
        int   s = clampi(__ldg(&g_csr_src[k]), 0, n - 1);
        float w = __ldg(&g_dinv[s]) * dnode;
        float4 v = __ldg(f4 + (size_t)s * 16 + c4);
        acc.x += w * v.x; acc.y += w * v.y;
        acc.z += w * v.z; acc.w += w * v.w;
    }

    acc.x += __shfl_down_sync(0xffffffffu, acc.x, 16);
    acc.y += __shfl_down_sync(0xffffffffu, acc.y, 16);
    acc.z += __shfl_down_sync(0xffffffffu, acc.z, 16);
    acc.w += __shfl_down_sync(0xffffffffu, acc.w, 16);

    if (half == 0)
        *(float4*)(outp + (size_t)node * 64 + c4 * 4) = acc;
}

__global__ void k_agg_l1(const float* __restrict__ x, int n, int ne) {
    agg_body<false>(x, g_agg1, nullptr, n, ne);
}
__global__ void k_agg_l2(float* __restrict__ out, const float* __restrict__ b4, int n, int ne) {
    agg_body<true>(g_hw, out, b4, n, ne);
}

// ---------------- bf16 split helper ----------------
__device__ __forceinline__ void bf16_split(float v, __nv_bfloat16& h, __nv_bfloat16& l) {
    h = __float2bfloat16(v);
    l = __float2bfloat16(v - __bfloat162float(h));
}

// ---------------- FUSED GEMM: g_hw = relu(g_agg1 @ W3 + b3) @ W4 -----------------
// Per 128-row tile, h never leaves shared memory. 3-pass hi/lo bf16 both stages.
constexpr int A1_LD = 72;    // bf16 elems (64+8)  -> conflict-free
constexpr int B1_LD = 136;   // (128+8)
constexpr int H_LDF = 132;   // fp32 h tile stride
constexpr int H_LD  = 136;   // bf16 h tiles stride
constexpr int B2_LD = 72;

// byte offsets
constexpr int O_A1H = 0;                              // [128][A1_LD] bf16 = 18432
constexpr int O_A1L = O_A1H + 128 * A1_LD * 2;        // 18432
constexpr int O_B1H = O_A1L + 128 * A1_LD * 2;        // 36864 [64][B1_LD] = 17408
constexpr int O_B1L = O_B1H + 64 * B1_LD * 2;         // 54272
constexpr int O_BIA = O_B1L + 64 * B1_LD * 2;         // 71680 [16][B1_LD] f32 = 8704
constexpr int O_B2H = O_BIA + 16 * B1_LD * 4;         // 80384 [128][B2_LD] = 18432
constexpr int O_B2L = O_B2H + 128 * B2_LD * 2;        // 98816
constexpr int O_HF  = O_B2L + 128 * B2_LD * 2;        // 117248 [128][H_LDF] f32 = 67584
constexpr int O_HH  = 0;                              // overlay A1H/A1L (36864 >= 34816)
constexpr int O_HL  = 36864;                          // overlay B1H/B1L (34816 fits)
constexpr int GF_SMEM = O_HF + 128 * H_LDF * 4;       // 184832

__global__ void __launch_bounds__(256) k_gemm_fused(const float* __restrict__ W3,
                                                    const float* __restrict__ b3,
                                                    const float* __restrict__ W4) {
    extern __shared__ __align__(16) char smem[];
    __nv_bfloat16* A1H = (__nv_bfloat16*)(smem + O_A1H);
    __nv_bfloat16* A1L = (__nv_bfloat16*)(smem + O_A1L);
    __nv_bfloat16* B1H = (__nv_bfloat16*)(smem + O_B1H);
    __nv_bfloat16* B1L = (__nv_bfloat16*)(smem + O_B1L);
    float*         BIA = (float*)        (smem + O_BIA);
    __nv_bfloat16* B2H = (__nv_bfloat16*)(smem + O_B2H);
    __nv_bfloat16* B2L = (__nv_bfloat16*)(smem + O_B2L);
    float*         HF  = (float*)        (smem + O_HF);
    __nv_bfloat16* HH  = (__nv_bfloat16*)(smem + O_HH);
    __nv_bfloat16* HL  = (__nv_bfloat16*)(smem + O_HL);

    int tid = threadIdx.x;
    int rb  = blockIdx.x * 128;
    int w   = tid >> 5;                    // warp -> 16-row strip

    // ---- phase 0: load A1, B1(W3), bias, B2(W4)
    for (int i = tid; i < 128 * 64; i += 256) {
        int r = i >> 6, c = i & 63;
        bf16_split(g_agg1[(size_t)(rb + r) * 64 + c], A1H[r * A1_LD + c], A1L[r * A1_LD + c]);
    }
    for (int i = tid; i < 64 * 128; i += 256) {
        int k = i >> 7, nn2 = i & 127;
        bf16_split(__ldg(&W3[i]), B1H[k * B1_LD + nn2], B1L[k * B1_LD + nn2]);
    }
    for (int i = tid; i < 16 * 128; i += 256) BIA[(i >> 7) * B1_LD + (i & 127)] = b3[i & 127];
    for (int i = tid; i < 128 * 64; i += 256) {
        int k = i >> 6, nn2 = i & 63;
        bf16_split(__ldg(&W4[i]), B2H[k * B2_LD + nn2], B2L[k * B2_LD + nn2]);
    }
    __syncthreads();

    // ---- phase 1: gemm1 -> relu -> fp32 h tile in smem
    {
        wmma::fragment<wmma::accumulator, 16, 16, 16, float> acc[8];
#pragma unroll
        for (int c = 0; c < 8; c++)
            wmma::load_matrix_sync(acc[c], BIA + c * 16, B1_LD, wmma::mem_row_major);
#pragma unroll
        for (int pass = 0; pass < 3; pass++) {
            const __nv_bfloat16* Ap = (pass == 2) ? A1L : A1H;
            const __nv_bfloat16* Bp = (pass == 1) ? B1L : B1H;
#pragma unroll
            for (int k = 0; k < 4; k++) {
                wmma::fragment<wmma::matrix_a, 16, 16, 16, __nv_bfloat16, wmma::row_major> a;
                wmma::load_matrix_sync(a, Ap + (w * 16) * A1_LD + k * 16, A1_LD);
#pragma unroll
                for (int c = 0; c < 8; c++) {
                    wmma::fragment<wmma::matrix_b, 16, 16, 16, __nv_bfloat16, wmma::row_major> b;
                    wmma::load_matrix_sync(b, Bp + (k * 16) * B1_LD + c * 16, B1_LD);
                    wmma::mma_sync(acc[c], a, b, acc[c]);
                }
            }
        }
#pragma unroll
        for (int c = 0; c < 8; c++) {
#pragma unroll
            for (int e = 0; e < acc[c].num_elements; e++)
                acc[c].x[e] = fmaxf(acc[c].x[e], 0.f);
            wmma::store_matrix_sync(HF + (w * 16) * H_LDF + c * 16, acc[c],
                                    H_LDF, wmma::mem_row_major);
        }
    }
    __syncthreads();

    // ---- phase 2: convert fp32 h -> bf16 hi/lo (overlaying dead phase-0 tiles)
    for (int i = tid; i < 128 * 128; i += 256) {
        int r = i >> 7, c = i & 127;
        bf16_split(HF[r * H_LDF + c], HH[r * H_LD + c], HL[r * H_LD + c]);
    }
    __syncthreads();

    // ---- phase 3: gemm2 -> g_hw
    {
        wmma::fragment<wmma::accumulator, 16, 16, 16, float> acc[4];
#pragma unroll
        for (int c = 0; c < 4; c++) wmma::fill_fragment(acc[c], 0.0f);
#pragma unroll
        for (int pass = 0; pass < 3; pass++) {
            const __nv_bfloat16* Ap = (pass == 2) ? HL : HH;
            const __nv_bfloat16* Bp = (pass == 1) ? B2L : B2H;
#pragma unroll
            for (int k = 0; k < 8; k++) {
                wmma::fragment<wmma::matrix_a, 16, 16, 16, __nv_bfloat16, wmma::row_major> a;
                wmma::load_matrix_sync(a, Ap + (w * 16) * H_LD + k * 16, H_LD);
#pragma unroll
                for (int c = 0; c < 4; c++) {
                    wmma::fragment<wmma::matrix_b, 16, 16, 16, __nv_bfloat16, wmma::row_major> b;
                    wmma::load_matrix_sync(b, Bp + (k * 16) * B2_LD + c * 16, B2_LD);
                    wmma::mma_sync(acc[c], a, b, acc[c]);
                }
            }
        }
#pragma unroll
        for (int c = 0; c < 4; c++)
            wmma::store_matrix_sync(g_hw + (size_t)(rb + w * 16) * OUT_C + c * 16,
                                    acc[c], OUT_C, wmma::mem_row_major);
    }
}

// ---------------- launch ----------------
extern "C" void kernel_launch(void* const* d_in, const int* in_sizes, int n_in,
                              void* d_out, int out_size) {
    const float* x    = (const float*)d_in[0];
    const int*   ei32 = (const int*)d_in[1];     // int32 OR int64 layout; probed on device
    const float* W3   = (const float*)d_in[2];
    const float* b3   = (const float*)d_in[3];
    const float* W4   = (const float*)d_in[4];
    const float* b4   = (const float*)d_in[5];
    float* out = (float*)d_out;

    int nn = in_sizes[0] / IN_C;   // 100000
    int ne = in_sizes[1] / 2;      // 1600000

    const int B   = 256;
    const int gN  = (nn + B - 1) / B;
    const int gE4 = (ne / 4 + B - 1) / B;                     // 4 edges per thread
    const int gA  = (int)(((long long)nn * 32 + B - 1) / B);  // warp per node
    const int gT  = NN_PAD / 128;                             // 782 tiles

    cudaFuncSetAttribute(k_gemm_fused, cudaFuncAttributeMaxDynamicSharedMemorySize, GF_SMEM);

    // CSR build
    k_detect_zero<<<gN, B>>>(ei32, nn);
    k_hist<<<gE4, B>>>(ei32, ne, nn);
    k_dinv_alloc<<<gN, B>>>(nn);
    k_fill<<<gE4, B>>>(ei32, ne, nn);

    // layer 1 agg, fused dense stack, layer 2 agg
    k_agg_l1<<<gA, B>>>(x, nn, ne);
    k_gemm_fused<<<gT, 256, GF_SMEM>>>(W3, b3, W4);
    k_agg_l2<<<gA, B>>>(out, b4, nn, ne);
}